// round 10
// baseline (speedup 1.0000x reference)
#include <cuda_runtime.h>
#include <cstdint>

#define T_STEPS 512
#define BATCH   64
#define IN_DIM  256
#define HID     512
#define OUT_DIM 256
#define G4      2048
#define NCTA    128

#define SW2_STRIDE  1032
#define SW2_FLOATS  (16 * SW2_STRIDE)      // 16512
#define SH_FLOATS   (HID * BATCH)          // 32768
#define SRED_STRIDE 20
#define SRED_SLICE  (64 * SRED_STRIDE)     // 1280
#define SRED_FLOATS (4 * SRED_SLICE)       // 5120
#define RSMEM_BYTES ((SW2_FLOATS + SH_FLOATS + SRED_FLOATS) * 4)   // 217600

#define OFF_H ((size_t)T_STEPS * BATCH * OUT_DIM)
#define OFF_C (OFF_H + (size_t)BATCH * HID)

typedef unsigned long long ull;

__device__ float    g_xg[(size_t)T_STEPS * G4 * BATCH];   // [t][g][b]
__device__ float    g_hs[(size_t)T_STEPS * HID * BATCH];  // [t][k][b]
__device__ float    g_bsum[G4];
__device__ unsigned g_bar1[256];   // 8 group counters at stride 32 (128B lines)
__device__ unsigned g_bar2;
__device__ unsigned g_flag;

__device__ __forceinline__ void ffma2(ull& d, ull a, ull b) {
    asm("fma.rn.f32x2 %0, %1, %2, %0;" : "+l"(d) : "l"(a), "l"(b));
}
__device__ __forceinline__ float2 unpack2(ull v) {
    float2 r; asm("mov.b64 {%0, %1}, %2;" : "=f"(r.x), "=f"(r.y) : "l"(v)); return r;
}
__device__ __forceinline__ float sigf(float x) {
    return __fdividef(1.f, 1.f + __expf(-x));
}
__device__ __forceinline__ float tanhfast(float x) {
    float e = __expf(-2.f * fabsf(x));
    float r = __fdividef(1.f - e, 1.f + e);
    return copysignf(r, x);
}
__device__ __forceinline__ void cp_async16(float* dst_smem, const float* src) {
    unsigned d = (unsigned)__cvta_generic_to_shared(dst_smem);
    asm volatile("cp.async.cg.shared.global [%0], [%1], 16;" :: "r"(d), "l"(src) : "memory");
}

__global__ void reset_kernel(const float* __restrict__ b_ih,
                             const float* __restrict__ b_hh) {
    int idx = blockIdx.x * blockDim.x + threadIdx.x;
    if (idx < 256) g_bar1[idx] = 0u;
    if (idx == 256) { g_bar2 = 0u; g_flag = 0u; }
    if (idx < G4) g_bsum[idx] = b_ih[idx] + b_hh[idx];
}

// ================= gemm1 (R5-proven): g_xg[t][g][b] = W_ih·x + bsum =========
__global__ __launch_bounds__(256) void gemm_xgate(
    const float* __restrict__ inp, const float* __restrict__ W)
{
    __shared__ float As[16][132];
    __shared__ float Bsw[16 * 196];
    const int t  = blockIdx.y;
    const int m0 = blockIdx.x * 128;
    const int tid = threadIdx.x;
    const int tx = tid & 15, ty = tid >> 4;
    const float* B = inp + (size_t)t * BATCH * IN_DIM;

    ull acc[4][4];
    #pragma unroll
    for (int i = 0; i < 4; i++)
        #pragma unroll
        for (int n = 0; n < 4; n++) acc[i][n] = 0ull;

    const int rr = tid >> 2;
    const int kq = (tid & 3) << 2;
    const int bbase = (rr >> 2) * 12 + (rr & 3) * 2;

    for (int k0 = 0; k0 < IN_DIM; k0 += 16) {
        #pragma unroll
        for (int u = 0; u < 2; u++) {
            int f4 = u * 256 + tid;
            int r2 = f4 >> 2, k2 = (f4 & 3) << 2;
            float4 v = *(const float4*)(W + (size_t)(m0 + r2) * IN_DIM + k0 + k2);
            As[k2 + 0][r2] = v.x; As[k2 + 1][r2] = v.y;
            As[k2 + 2][r2] = v.z; As[k2 + 3][r2] = v.w;
        }
        {
            float4 v = *(const float4*)(B + (size_t)rr * IN_DIM + k0 + kq);
            *(float2*)&Bsw[(kq + 0) * 196 + bbase] = make_float2(v.x, v.x);
            *(float2*)&Bsw[(kq + 1) * 196 + bbase] = make_float2(v.y, v.y);
            *(float2*)&Bsw[(kq + 2) * 196 + bbase] = make_float2(v.z, v.z);
            *(float2*)&Bsw[(kq + 3) * 196 + bbase] = make_float2(v.w, v.w);
        }
        __syncthreads();
        #pragma unroll
        for (int kk = 0; kk < 16; kk++) {
            ulonglong2 a01 = *(const ulonglong2*)&As[kk][ty * 8];
            ulonglong2 a23 = *(const ulonglong2*)&As[kk][ty * 8 + 4];
            const float* bp = Bsw + kk * 196 + tx * 12;
            ulonglong2 b01 = *(const ulonglong2*)bp;
            ulonglong2 b23 = *(const ulonglong2*)(bp + 4);
            ffma2(acc[0][0], a01.x, b01.x); ffma2(acc[1][0], a01.y, b01.x);
            ffma2(acc[2][0], a23.x, b01.x); ffma2(acc[3][0], a23.y, b01.x);
            ffma2(acc[0][1], a01.x, b01.y); ffma2(acc[1][1], a01.y, b01.y);
            ffma2(acc[2][1], a23.x, b01.y); ffma2(acc[3][1], a23.y, b01.y);
            ffma2(acc[0][2], a01.x, b23.x); ffma2(acc[1][2], a01.y, b23.x);
            ffma2(acc[2][2], a23.x, b23.x); ffma2(acc[3][2], a23.y, b23.x);
            ffma2(acc[0][3], a01.x, b23.y); ffma2(acc[1][3], a01.y, b23.y);
            ffma2(acc[2][3], a23.x, b23.y); ffma2(acc[3][3], a23.y, b23.y);
        }
        __syncthreads();
    }

    float* C = g_xg + ((size_t)t * G4 + m0) * BATCH;
    #pragma unroll
    for (int mp = 0; mp < 4; mp++) {
        float2 u0 = unpack2(acc[mp][0]);
        float2 u1 = unpack2(acc[mp][1]);
        float2 u2 = unpack2(acc[mp][2]);
        float2 u3 = unpack2(acc[mp][3]);
        int mA = ty * 8 + mp * 2, mB = mA + 1;
        float bA = g_bsum[m0 + mA], bB = g_bsum[m0 + mB];
        *(float4*)(C + (size_t)mA * BATCH + tx * 4) =
            make_float4(u0.x + bA, u1.x + bA, u2.x + bA, u3.x + bA);
        *(float4*)(C + (size_t)mB * BATCH + tx * 4) =
            make_float4(u0.y + bB, u1.y + bB, u2.y + bB, u3.y + bB);
    }
}

// ================= gemm2 (R5-proven): out[t][b][o] = h·W_out^T + b_out ======
__global__ __launch_bounds__(256) void gemm_out(
    const float* __restrict__ Wout, const float* __restrict__ bout,
    float* __restrict__ out)
{
    __shared__ float As2[16][68];
    __shared__ float Wsw[16 * 196];
    const int t  = blockIdx.y;
    const int n0 = blockIdx.x * 64;
    const int tid = threadIdx.x;
    const int tx = tid & 15, ty = tid >> 4;
    const float* A = g_hs + (size_t)t * HID * BATCH;

    ull acc[2][4];
    #pragma unroll
    for (int i = 0; i < 2; i++)
        #pragma unroll
        for (int n = 0; n < 4; n++) acc[i][n] = 0ull;

    const int rr = tid >> 2;
    const int kq = (tid & 3) << 2;
    const int obase = (rr >> 2) * 12 + (rr & 3) * 2;
    const int akk = tid >> 4, ac4 = (tid & 15) * 4;

    for (int k0 = 0; k0 < HID; k0 += 16) {
        *(float4*)&As2[akk][ac4] = *(const float4*)(A + (size_t)(k0 + akk) * BATCH + ac4);
        {
            float4 v = *(const float4*)(Wout + (size_t)(n0 + rr) * HID + k0 + kq);
            *(float2*)&Wsw[(kq + 0) * 196 + obase] = make_float2(v.x, v.x);
            *(float2*)&Wsw[(kq + 1) * 196 + obase] = make_float2(v.y, v.y);
            *(float2*)&Wsw[(kq + 2) * 196 + obase] = make_float2(v.z, v.z);
            *(float2*)&Wsw[(kq + 3) * 196 + obase] = make_float2(v.w, v.w);
        }
        __syncthreads();
        #pragma unroll
        for (int kk = 0; kk < 16; kk++) {
            ulonglong2 a = *(const ulonglong2*)&As2[kk][ty * 4];
            const float* wp = Wsw + kk * 196 + tx * 12;
            ulonglong2 w01 = *(const ulonglong2*)wp;
            ulonglong2 w23 = *(const ulonglong2*)(wp + 4);
            ffma2(acc[0][0], a.x, w01.x); ffma2(acc[1][0], a.y, w01.x);
            ffma2(acc[0][1], a.x, w01.y); ffma2(acc[1][1], a.y, w01.y);
            ffma2(acc[0][2], a.x, w23.x); ffma2(acc[1][2], a.y, w23.x);
            ffma2(acc[0][3], a.x, w23.y); ffma2(acc[1][3], a.y, w23.y);
        }
        __syncthreads();
    }

    float4 bb = *(const float4*)(bout + n0 + tx * 4);
    float2 u[2][4];
    #pragma unroll
    for (int p = 0; p < 2; p++)
        #pragma unroll
        for (int n = 0; n < 4; n++) u[p][n] = unpack2(acc[p][n]);
    #pragma unroll
    for (int bi = 0; bi < 4; bi++) {
        int p = bi >> 1;
        float4 r;
        if (bi & 1) r = make_float4(u[p][0].y + bb.x, u[p][1].y + bb.y,
                                    u[p][2].y + bb.z, u[p][3].y + bb.w);
        else        r = make_float4(u[p][0].x + bb.x, u[p][1].x + bb.y,
                                    u[p][2].x + bb.z, u[p][3].x + bb.w);
        *(float4*)(out + ((size_t)t * BATCH + ty * 4 + bi) * OUT_DIM + n0 + tx * 4) = r;
    }
}

// ================= persistent recurrent kernel =================
// h staged through SMEM per K-slice (kills 4x duplicated L2 traffic);
// 2-level grid barrier (kills single-line atomic serialization).
__device__ __forceinline__ void loadh8s(ulonglong2* hb, const float* p) {
    #pragma unroll
    for (int i = 0; i < 8; i++)
        hb[i] = *(const ulonglong2*)(p + (size_t)i * BATCH);
}
__device__ __forceinline__ void comp8(ull acc[4][2], const ulonglong2* hb,
                                      const float* wb0, int kl) {
    #pragma unroll
    for (int q = 0; q < 4; q++) {
        const float* wr = wb0 + q * 4 * SW2_STRIDE + 2 * kl;
        ulonglong2 w0 = *(const ulonglong2*)(wr);
        ulonglong2 w1 = *(const ulonglong2*)(wr + 4);
        ulonglong2 w2 = *(const ulonglong2*)(wr + 8);
        ulonglong2 w3 = *(const ulonglong2*)(wr + 12);
        ffma2(acc[q][0], hb[0].x, w0.x); ffma2(acc[q][1], hb[0].y, w0.x);
        ffma2(acc[q][0], hb[1].x, w0.y); ffma2(acc[q][1], hb[1].y, w0.y);
        ffma2(acc[q][0], hb[2].x, w1.x); ffma2(acc[q][1], hb[2].y, w1.x);
        ffma2(acc[q][0], hb[3].x, w1.y); ffma2(acc[q][1], hb[3].y, w1.y);
        ffma2(acc[q][0], hb[4].x, w2.x); ffma2(acc[q][1], hb[4].y, w2.x);
        ffma2(acc[q][0], hb[5].x, w2.y); ffma2(acc[q][1], hb[5].y, w2.y);
        ffma2(acc[q][0], hb[6].x, w3.x); ffma2(acc[q][1], hb[6].y, w3.x);
        ffma2(acc[q][0], hb[7].x, w3.y); ffma2(acc[q][1], hb[7].y, w3.y);
    }
}

__global__ void __launch_bounds__(256, 1)
lstm_recurrent(const float* __restrict__ W_hh, float* __restrict__ out)
{
    extern __shared__ float smem[];
    float* sW2  = smem;                        // 16 x 1032 (splatted weights)
    float* sH   = smem + SW2_FLOATS;           // [512 k][64 b]
    float* sRed = sH + SH_FLOATS;              // 4 x 64 x 20

    const int tid = threadIdx.x;
    const int j0  = blockIdx.x << 2;
    // FMA role
    const int hk  = tid >> 6;
    const int s   = tid & 63;
    const int ii  = s >> 4;
    const int bg  = (s & 15) << 2;
    // epilogue role (one output per thread)
    const int jj  = tid >> 6;
    const int bo  = tid & 63;
    const int j_out = j0 + jj;
    const int s2  = jj * 16 + (bo >> 2);
    const int bb2 = bo & 3;

    // stage W_hh pre-splatted
    #pragma unroll
    for (int u = 0; u < 8; u++) {
        int f4 = u * 256 + tid;
        int rr = f4 >> 7;
        int kk = (f4 & 127) << 2;
        int q = rr >> 2, iw = rr & 3;
        float4 v = *(const float4*)(W_hh + (size_t)(q * HID + j0 + iw) * HID + kk);
        float* d = sW2 + rr * SW2_STRIDE + 2 * kk;
        *(float4*)(d    ) = make_float4(v.x, v.x, v.y, v.y);
        *(float4*)(d + 4) = make_float4(v.z, v.z, v.w, v.w);
    }
    __syncthreads();

    float creg = 0.f;
    const float* wb0 = sW2 + ii * SW2_STRIDE + hk * 256;

    for (int t = 0; t < T_STEPS; t++) {
        // xg for this thread's output (DRAM latency hidden under FMA loop)
        float xg[4];
        #pragma unroll
        for (int q = 0; q < 4; q++)
            xg[q] = __ldg(g_xg + ((size_t)t * G4 + q * HID + j_out) * BATCH + bo);

        ull acc[4][2];
        #pragma unroll
        for (int q = 0; q < 4; q++) { acc[q][0] = 0ull; acc[q][1] = 0ull; }

        if (t > 0) {
            const float* hsrc = g_hs + ((size_t)(t - 1) * HID + hk * 128) * BATCH;
            float* dst = sH + hk * 128 * BATCH;
            // slice loads its own 32KB, two 16KB chunks
            #pragma unroll
            for (int u = 0; u < 16; u++) {
                int f4 = u * 64 + s;
                cp_async16(dst + f4 * 4, hsrc + (size_t)f4 * 4);
            }
            asm volatile("cp.async.commit_group;" ::: "memory");
            #pragma unroll
            for (int u = 16; u < 32; u++) {
                int f4 = u * 64 + s;
                cp_async16(dst + f4 * 4, hsrc + (size_t)f4 * 4);
            }
            asm volatile("cp.async.commit_group;" ::: "memory");

            const float* hbase = sH + hk * 128 * BATCH + bg;

            asm volatile("cp.async.wait_group 1;" ::: "memory");
            asm volatile("bar.sync %0, 64;" :: "r"(1 + hk) : "memory");
            #pragma unroll 2
            for (int kl = 0; kl < 64; kl += 8) {
                ulonglong2 hb[8];
                loadh8s(hb, hbase + (size_t)kl * BATCH);
                comp8(acc, hb, wb0, kl);
            }
            asm volatile("cp.async.wait_group 0;" ::: "memory");
            asm volatile("bar.sync %0, 64;" :: "r"(1 + hk) : "memory");
            #pragma unroll 2
            for (int kl = 64; kl < 128; kl += 8) {
                ulonglong2 hb[8];
                loadh8s(hb, hbase + (size_t)kl * BATCH);
                comp8(acc, hb, wb0, kl);
            }
        }

        // publish partials: [hk][s][batch-in-quad x gate]
        {
            float2 lo[4], hi[4];
            #pragma unroll
            for (int q = 0; q < 4; q++) { lo[q] = unpack2(acc[q][0]); hi[q] = unpack2(acc[q][1]); }
            float* p = sRed + hk * SRED_SLICE + s * SRED_STRIDE;
            *(float4*)(p + 0)  = make_float4(lo[0].x, lo[1].x, lo[2].x, lo[3].x);
            *(float4*)(p + 4)  = make_float4(lo[0].y, lo[1].y, lo[2].y, lo[3].y);
            *(float4*)(p + 8)  = make_float4(hi[0].x, hi[1].x, hi[2].x, hi[3].x);
            *(float4*)(p + 12) = make_float4(hi[0].y, hi[1].y, hi[2].y, hi[3].y);
        }
        __syncthreads();

        // epilogue: one output per thread
        {
            const float* rp = sRed + s2 * SRED_STRIDE + bb2 * 4;
            float4 v0 = *(const float4*)(rp);
            float4 v1 = *(const float4*)(rp + SRED_SLICE);
            float4 v2 = *(const float4*)(rp + 2 * SRED_SLICE);
            float4 v3 = *(const float4*)(rp + 3 * SRED_SLICE);
            float a0 = v0.x + v1.x + v2.x + v3.x + xg[0];
            float a1 = v0.y + v1.y + v2.y + v3.y + xg[1];
            float a2 = v0.z + v1.z + v2.z + v3.z + xg[2];
            float a3 = v0.w + v1.w + v2.w + v3.w + xg[3];
            float iv = sigf(a0);
            float fv = sigf(a1);
            float gv = tanhfast(a2);
            float ov = sigf(a3);
            creg = fv * creg + iv * gv;
            float hn = ov * tanhfast(creg);
            g_hs[((size_t)t * HID + j_out) * BATCH + bo] = hn;
            if (t == T_STEPS - 1) {
                out[OFF_H + (size_t)bo * HID + j_out] = hn;
                out[OFF_C + (size_t)bo * HID + j_out] = creg;
            }
        }
        __syncthreads();

        // 2-level grid barrier: 8 spread group lines -> root -> flag
        if (tid == 0) {
            unsigned grp = (unsigned)blockIdx.x >> 4;
            unsigned r1;
            asm volatile("atom.acq_rel.gpu.global.add.u32 %0, [%1], %2;"
                         : "=r"(r1) : "l"(&g_bar1[grp * 32]), "r"(1u) : "memory");
            if (r1 == (unsigned)(t + 1) * 16 - 1) {
                unsigned r2;
                asm volatile("atom.acq_rel.gpu.global.add.u32 %0, [%1], %2;"
                             : "=r"(r2) : "l"(&g_bar2), "r"(1u) : "memory");
                if (r2 == (unsigned)(t + 1) * 8 - 1)
                    asm volatile("st.release.gpu.global.u32 [%0], %1;"
                                 :: "l"(&g_flag), "r"((unsigned)(t + 1)) : "memory");
            }
            unsigned v;
            do {
                asm volatile("ld.acquire.gpu.global.u32 %0, [%1];"
                             : "=r"(v) : "l"(&g_flag) : "memory");
            } while (v < (unsigned)(t + 1));
        }
        __syncthreads();
    }
}

// ---------------- launch ----------------
extern "C" void kernel_launch(void* const* d_in, const int* in_sizes, int n_in,
                              void* d_out, int out_size) {
    const float* inputs = (const float*)d_in[0];
    const float* W_ih   = (const float*)d_in[1];
    const float* W_hh   = (const float*)d_in[2];
    const float* b_ih   = (const float*)d_in[3];
    const float* b_hh   = (const float*)d_in[4];
    const float* W_out  = (const float*)d_in[5];
    const float* b_out  = (const float*)d_in[6];
    float* out = (float*)d_out;

    static int attr_done = 0;
    if (!attr_done) {
        cudaFuncSetAttribute(lstm_recurrent,
                             cudaFuncAttributeMaxDynamicSharedMemorySize, RSMEM_BYTES);
        attr_done = 1;
    }

    reset_kernel<<<16, 256>>>(b_ih, b_hh);

    gemm_xgate<<<dim3(G4 / 128, T_STEPS), 256>>>(inputs, W_ih);

    lstm_recurrent<<<NCTA, 256, RSMEM_BYTES>>>(W_hh, out);

    gemm_out<<<dim3(OUT_DIM / 64, T_STEPS), 256>>>(W_out, b_out, out);
}

// round 11
// speedup vs baseline: 1.0089x; 1.0089x over previous
#include <cuda_runtime.h>
#include <cstdint>

#define T_STEPS 512
#define BATCH   64
#define IN_DIM  256
#define HID     512
#define OUT_DIM 256
#define G4      2048
#define NCTA    128

#define SW2_STRIDE  1032
#define SW2_FLOATS  (16 * SW2_STRIDE)      // 16512
#define SRED_STRIDE 20
#define SRED_SLICE  (64 * SRED_STRIDE)     // 1280
#define SRED_FLOATS (8 * SRED_SLICE)       // 10240
#define RSMEM_BYTES ((SW2_FLOATS + SRED_FLOATS) * 4)   // 107008

#define OFF_H ((size_t)T_STEPS * BATCH * OUT_DIM)
#define OFF_C (OFF_H + (size_t)BATCH * HID)

typedef unsigned long long ull;

__device__ float    g_xg[(size_t)T_STEPS * G4 * BATCH];   // [t][g][b]
__device__ float    g_hs[(size_t)T_STEPS * HID * BATCH];  // [t][k][b]
__device__ float    g_bsum[G4];
__device__ unsigned g_bar;
__device__ unsigned g_flag;

__device__ __forceinline__ void ffma2(ull& d, ull a, ull b) {
    asm("fma.rn.f32x2 %0, %1, %2, %0;" : "+l"(d) : "l"(a), "l"(b));
}
__device__ __forceinline__ float2 unpack2(ull v) {
    float2 r; asm("mov.b64 {%0, %1}, %2;" : "=f"(r.x), "=f"(r.y) : "l"(v)); return r;
}
__device__ __forceinline__ float sigf(float x) {
    return __fdividef(1.f, 1.f + __expf(-x));
}
__device__ __forceinline__ float tanhfast(float x) {
    float e = __expf(-2.f * fabsf(x));
    float r = __fdividef(1.f - e, 1.f + e);
    return copysignf(r, x);
}

__global__ void reset_kernel(const float* __restrict__ b_ih,
                             const float* __restrict__ b_hh) {
    int idx = blockIdx.x * blockDim.x + threadIdx.x;
    if (idx == 0) { g_bar = 0u; g_flag = 0u; }
    if (idx < G4) g_bsum[idx] = b_ih[idx] + b_hh[idx];
}

// ============ gemm_xgate v2: g_xg[t][g][b] = W_ih·x + bsum ============
// grid (16, 512), 256 thr. Tile 128g x 64b, BK=16, micro 8m(4 pairs) x 4n.
// FFMA2 over g-pairs; B stored as contiguous splat pairs (no MOVs, 1wf loads).
__global__ __launch_bounds__(256) void gemm_xgate(
    const float* __restrict__ inp, const float* __restrict__ W)
{
    __shared__ float As [16][132];   // [k][g]
    __shared__ float Bs2[16][136];   // [k][2b splat]
    const int t  = blockIdx.y;
    const int m0 = blockIdx.x * 128;
    const int tid = threadIdx.x;
    const int tm = tid & 15;         // g-block (8 rows = 4 pairs)
    const int tn = tid >> 4;         // b-block (4 cols)
    const float* B = inp + (size_t)t * BATCH * IN_DIM;

    ull acc[4][4];
    #pragma unroll
    for (int i = 0; i < 4; i++)
        #pragma unroll
        for (int n = 0; n < 4; n++) acc[i][n] = 0ull;

    const int brr = tid >> 2;
    const int bkq = (tid & 3) << 2;

    for (int k0 = 0; k0 < IN_DIM; k0 += 16) {
        #pragma unroll
        for (int u = 0; u < 2; u++) {
            int f4 = u * 256 + tid;
            int rr = f4 >> 2, kq = (f4 & 3) << 2;
            float4 v = *(const float4*)(W + (size_t)(m0 + rr) * IN_DIM + k0 + kq);
            As[kq + 0][rr] = v.x; As[kq + 1][rr] = v.y;
            As[kq + 2][rr] = v.z; As[kq + 3][rr] = v.w;
        }
        {
            float4 v = *(const float4*)(B + (size_t)brr * IN_DIM + k0 + bkq);
            *(float2*)&Bs2[bkq + 0][2 * brr] = make_float2(v.x, v.x);
            *(float2*)&Bs2[bkq + 1][2 * brr] = make_float2(v.y, v.y);
            *(float2*)&Bs2[bkq + 2][2 * brr] = make_float2(v.z, v.z);
            *(float2*)&Bs2[bkq + 3][2 * brr] = make_float2(v.w, v.w);
        }
        __syncthreads();
        #pragma unroll
        for (int kk = 0; kk < 16; kk++) {
            ulonglong2 a01 = *(const ulonglong2*)&As[kk][tm * 8];
            ulonglong2 a23 = *(const ulonglong2*)&As[kk][tm * 8 + 4];
            ulonglong2 b01 = *(const ulonglong2*)&Bs2[kk][tn * 8];
            ulonglong2 b23 = *(const ulonglong2*)&Bs2[kk][tn * 8 + 4];
            ffma2(acc[0][0], a01.x, b01.x); ffma2(acc[1][0], a01.y, b01.x);
            ffma2(acc[2][0], a23.x, b01.x); ffma2(acc[3][0], a23.y, b01.x);
            ffma2(acc[0][1], a01.x, b01.y); ffma2(acc[1][1], a01.y, b01.y);
            ffma2(acc[2][1], a23.x, b01.y); ffma2(acc[3][1], a23.y, b01.y);
            ffma2(acc[0][2], a01.x, b23.x); ffma2(acc[1][2], a01.y, b23.x);
            ffma2(acc[2][2], a23.x, b23.x); ffma2(acc[3][2], a23.y, b23.x);
            ffma2(acc[0][3], a01.x, b23.y); ffma2(acc[1][3], a01.y, b23.y);
            ffma2(acc[2][3], a23.x, b23.y); ffma2(acc[3][3], a23.y, b23.y);
        }
        __syncthreads();
    }

    float* C = g_xg + ((size_t)t * G4 + m0) * BATCH;
    #pragma unroll
    for (int mp = 0; mp < 4; mp++) {
        float2 u0 = unpack2(acc[mp][0]);
        float2 u1 = unpack2(acc[mp][1]);
        float2 u2 = unpack2(acc[mp][2]);
        float2 u3 = unpack2(acc[mp][3]);
        int mA = tm * 8 + mp * 2, mB = mA + 1;
        float bA = g_bsum[m0 + mA], bB = g_bsum[m0 + mB];
        *(float4*)(C + (size_t)mA * BATCH + tn * 4) =
            make_float4(u0.x + bA, u1.x + bA, u2.x + bA, u3.x + bA);
        *(float4*)(C + (size_t)mB * BATCH + tn * 4) =
            make_float4(u0.y + bB, u1.y + bB, u2.y + bB, u3.y + bB);
    }
}

// ============ gemm_out v2: out[t][b][o] = h·W_out^T + b_out ============
// grid (2, 512), 256 thr. Tile 64b x 128o, BK=16, micro 8m(4 b-pairs) x 4n.
__global__ __launch_bounds__(256) void gemm_out(
    const float* __restrict__ Wout, const float* __restrict__ bout,
    float* __restrict__ out)
{
    __shared__ float As2[16][68];    // [k][b] direct copy
    __shared__ float Bs2[16][264];   // [k][2o splat]
    const int t  = blockIdx.y;
    const int o0 = blockIdx.x * 128;
    const int tid = threadIdx.x;
    const int tm = tid & 7;          // b-block (8 rows = 4 pairs)
    const int tn = tid >> 3;         // o-block (4 cols), 0..31
    const float* A = g_hs + (size_t)t * HID * BATCH;

    ull acc[4][4];
    #pragma unroll
    for (int i = 0; i < 4; i++)
        #pragma unroll
        for (int n = 0; n < 4; n++) acc[i][n] = 0ull;

    const int akk = tid >> 4, ac4 = (tid & 15) * 4;

    for (int k0 = 0; k0 < HID; k0 += 16) {
        *(float4*)&As2[akk][ac4] = *(const float4*)(A + (size_t)(k0 + akk) * BATCH + ac4);
        #pragma unroll
        for (int u = 0; u < 2; u++) {
            int f4 = u * 256 + tid;
            int rr = f4 >> 2, kq = (f4 & 3) << 2;
            float4 v = *(const float4*)(Wout + (size_t)(o0 + rr) * HID + k0 + kq);
            *(float2*)&Bs2[kq + 0][2 * rr] = make_float2(v.x, v.x);
            *(float2*)&Bs2[kq + 1][2 * rr] = make_float2(v.y, v.y);
            *(float2*)&Bs2[kq + 2][2 * rr] = make_float2(v.z, v.z);
            *(float2*)&Bs2[kq + 3][2 * rr] = make_float2(v.w, v.w);
        }
        __syncthreads();
        #pragma unroll
        for (int kk = 0; kk < 16; kk++) {
            ulonglong2 a01 = *(const ulonglong2*)&As2[kk][tm * 8];
            ulonglong2 a23 = *(const ulonglong2*)&As2[kk][tm * 8 + 4];
            ulonglong2 b01 = *(const ulonglong2*)&Bs2[kk][tn * 8];
            ulonglong2 b23 = *(const ulonglong2*)&Bs2[kk][tn * 8 + 4];
            ffma2(acc[0][0], a01.x, b01.x); ffma2(acc[1][0], a01.y, b01.x);
            ffma2(acc[2][0], a23.x, b01.x); ffma2(acc[3][0], a23.y, b01.x);
            ffma2(acc[0][1], a01.x, b01.y); ffma2(acc[1][1], a01.y, b01.y);
            ffma2(acc[2][1], a23.x, b01.y); ffma2(acc[3][1], a23.y, b01.y);
            ffma2(acc[0][2], a01.x, b23.x); ffma2(acc[1][2], a01.y, b23.x);
            ffma2(acc[2][2], a23.x, b23.x); ffma2(acc[3][2], a23.y, b23.x);
            ffma2(acc[0][3], a01.x, b23.y); ffma2(acc[1][3], a01.y, b23.y);
            ffma2(acc[2][3], a23.x, b23.y); ffma2(acc[3][3], a23.y, b23.y);
        }
        __syncthreads();
    }

    float4 bb = *(const float4*)(bout + o0 + tn * 4);
    #pragma unroll
    for (int mp = 0; mp < 4; mp++) {
        float2 u0 = unpack2(acc[mp][0]);
        float2 u1 = unpack2(acc[mp][1]);
        float2 u2 = unpack2(acc[mp][2]);
        float2 u3 = unpack2(acc[mp][3]);
        int bA = tm * 8 + mp * 2, bB = bA + 1;
        *(float4*)(out + ((size_t)t * BATCH + bA) * OUT_DIM + o0 + tn * 4) =
            make_float4(u0.x + bb.x, u1.x + bb.y, u2.x + bb.z, u3.x + bb.w);
        *(float4*)(out + ((size_t)t * BATCH + bB) * OUT_DIM + o0 + tn * 4) =
            make_float4(u0.y + bb.x, u1.y + bb.y, u2.y + bb.z, u3.y + bb.w);
    }
}

// ================= persistent recurrent kernel (512 threads) =================
// 8 K-slices x 64 threads; thread = 1 column x 4 gates x 4 batch, 64 k.
__device__ __forceinline__ void loadh8(ulonglong2* hb, const float* p) {
    #pragma unroll
    for (int i = 0; i < 8; i++)
        hb[i] = __ldg((const ulonglong2*)(p + (size_t)i * BATCH));
}
__device__ __forceinline__ void comp8(ull acc[4][2], const ulonglong2* hb,
                                      const float* wb0, int kl) {
    #pragma unroll
    for (int q = 0; q < 4; q++) {
        const float* wr = wb0 + q * 4 * SW2_STRIDE + 2 * kl;
        ulonglong2 w0 = *(const ulonglong2*)(wr);
        ulonglong2 w1 = *(const ulonglong2*)(wr + 4);
        ulonglong2 w2 = *(const ulonglong2*)(wr + 8);
        ulonglong2 w3 = *(const ulonglong2*)(wr + 12);
        ffma2(acc[q][0], hb[0].x, w0.x); ffma2(acc[q][1], hb[0].y, w0.x);
        ffma2(acc[q][0], hb[1].x, w0.y); ffma2(acc[q][1], hb[1].y, w0.y);
        ffma2(acc[q][0], hb[2].x, w1.x); ffma2(acc[q][1], hb[2].y, w1.x);
        ffma2(acc[q][0], hb[3].x, w1.y); ffma2(acc[q][1], hb[3].y, w1.y);
        ffma2(acc[q][0], hb[4].x, w2.x); ffma2(acc[q][1], hb[4].y, w2.x);
        ffma2(acc[q][0], hb[5].x, w2.y); ffma2(acc[q][1], hb[5].y, w2.y);
        ffma2(acc[q][0], hb[6].x, w3.x); ffma2(acc[q][1], hb[6].y, w3.x);
        ffma2(acc[q][0], hb[7].x, w3.y); ffma2(acc[q][1], hb[7].y, w3.y);
    }
}

__global__ void __launch_bounds__(512, 1)
lstm_recurrent(const float* __restrict__ W_hh, float* __restrict__ out)
{
    extern __shared__ float smem[];
    float* sW2  = smem;                 // 16 x 1032 (splatted W_hh rows)
    float* sRed = smem + SW2_FLOATS;    // 8 slices x 64 x 20

    const int tid = threadIdx.x;
    const int j0  = blockIdx.x << 2;
    // FMA role: slice hk (64 k), (ii, bg)
    const int hk  = tid >> 6;           // 0..7
    const int s   = tid & 63;
    const int ii  = s >> 4;
    const int bg  = (s & 15) << 2;
    // epilogue role (tid < 256): one (column, batch) output
    const int jj  = (tid >> 6) & 3;
    const int bo  = tid & 63;
    const int j_out = j0 + jj;
    const int s2  = jj * 16 + (bo >> 2);
    const int bb2 = bo & 3;

    // stage W_hh pre-splatted (2048 float4s, 512 threads -> 4 iters)
    #pragma unroll
    for (int u = 0; u < 4; u++) {
        int f4 = u * 512 + tid;
        int rr = f4 >> 7;
        int kk = (f4 & 127) << 2;
        int q = rr >> 2, iw = rr & 3;
        float4 v = *(const float4*)(W_hh + (size_t)(q * HID + j0 + iw) * HID + kk);
        float* d = sW2 + rr * SW2_STRIDE + 2 * kk;
        *(float4*)(d    ) = make_float4(v.x, v.x, v.y, v.y);
        *(float4*)(d + 4) = make_float4(v.z, v.z, v.w, v.w);
    }
    __syncthreads();

    float creg = 0.f;
    const float* wb0 = sW2 + ii * SW2_STRIDE + hk * 128;   // slice k-offset (x2 splat)

    for (int t = 0; t < T_STEPS; t++) {
        float xg[4];
        if (tid < 256) {
            #pragma unroll
            for (int q = 0; q < 4; q++)
                xg[q] = __ldg(g_xg + ((size_t)t * G4 + q * HID + j_out) * BATCH + bo);
        }

        ull acc[4][2];
        #pragma unroll
        for (int q = 0; q < 4; q++) { acc[q][0] = 0ull; acc[q][1] = 0ull; }

        if (t > 0) {
            const float* hsrc = g_hs + ((size_t)(t - 1) * HID + hk * 64) * BATCH + bg;
            ulonglong2 hb0[8], hb1[8];
            loadh8(hb0, hsrc);
            #pragma unroll
            for (int g2 = 0; g2 < 4; g2++) {
                loadh8(hb1, hsrc + (size_t)(2 * g2 + 1) * 8 * BATCH);
                comp8(acc, hb0, wb0, 2 * g2 * 8);
                loadh8(hb0, hsrc + (size_t)(2 * g2 + 2) * 8 * BATCH);  // overread stays in-array
                comp8(acc, hb1, wb0, (2 * g2 + 1) * 8);
            }
        }

        // all 8 slices publish partials
        {
            float2 lo[4], hi[4];
            #pragma unroll
            for (int q = 0; q < 4; q++) { lo[q] = unpack2(acc[q][0]); hi[q] = unpack2(acc[q][1]); }
            float* p = sRed + hk * SRED_SLICE + s * SRED_STRIDE;
            *(float4*)(p + 0)  = make_float4(lo[0].x, lo[1].x, lo[2].x, lo[3].x);
            *(float4*)(p + 4)  = make_float4(lo[0].y, lo[1].y, lo[2].y, lo[3].y);
            *(float4*)(p + 8)  = make_float4(hi[0].x, hi[1].x, hi[2].x, hi[3].x);
            *(float4*)(p + 12) = make_float4(hi[0].y, hi[1].y, hi[2].y, hi[3].y);
        }
        __syncthreads();

        if (tid < 256) {
            const float* rp = sRed + s2 * SRED_STRIDE + bb2 * 4;
            float4 v0 = *(const float4*)(rp);
            float4 v1 = *(const float4*)(rp + 1 * SRED_SLICE);
            float4 v2 = *(const float4*)(rp + 2 * SRED_SLICE);
            float4 v3 = *(const float4*)(rp + 3 * SRED_SLICE);
            float4 v4 = *(const float4*)(rp + 4 * SRED_SLICE);
            float4 v5 = *(const float4*)(rp + 5 * SRED_SLICE);
            float4 v6 = *(const float4*)(rp + 6 * SRED_SLICE);
            float4 v7 = *(const float4*)(rp + 7 * SRED_SLICE);
            float a0 = ((v0.x + v1.x) + (v2.x + v3.x)) + ((v4.x + v5.x) + (v6.x + v7.x)) + xg[0];
            float a1 = ((v0.y + v1.y) + (v2.y + v3.y)) + ((v4.y + v5.y) + (v6.y + v7.y)) + xg[1];
            float a2 = ((v0.z + v1.z) + (v2.z + v3.z)) + ((v4.z + v5.z) + (v6.z + v7.z)) + xg[2];
            float a3 = ((v0.w + v1.w) + (v2.w + v3.w)) + ((v4.w + v5.w) + (v6.w + v7.w)) + xg[3];
            float iv = sigf(a0);
            float fv = sigf(a1);
            float gv = tanhfast(a2);
            float ov = sigf(a3);
            creg = fv * creg + iv * gv;
            float hn = ov * tanhfast(creg);
            g_hs[((size_t)t * HID + j_out) * BATCH + bo] = hn;
            if (t == T_STEPS - 1) {
                out[OFF_H + (size_t)bo * HID + j_out] = hn;
                out[OFF_C + (size_t)bo * HID + j_out] = creg;
            }
        }
        __syncthreads();

        // grid barrier: single release-atomic + flag (R5-proven)
        if (tid == 0) {
            unsigned target = (unsigned)(t + 1) * NCTA;
            unsigned ret;
            asm volatile("atom.release.gpu.global.add.u32 %0, [%1], %2;"
                         : "=r"(ret) : "l"(&g_bar), "r"(1u) : "memory");
            if (ret == target - 1) {
                asm volatile("st.release.gpu.global.u32 [%0], %1;"
                             :: "l"(&g_flag), "r"((unsigned)(t + 1)) : "memory");
            } else {
                unsigned v;
                do {
                    asm volatile("ld.acquire.gpu.global.u32 %0, [%1];"
                                 : "=r"(v) : "l"(&g_flag) : "memory");
                } while (v < (unsigned)(t + 1));
            }
        }
        __syncthreads();
    }
}

// ---------------- launch ----------------
extern "C" void kernel_launch(void* const* d_in, const int* in_sizes, int n_in,
                              void* d_out, int out_size) {
    const float* inputs = (const float*)d_in[0];
    const float* W_ih   = (const float*)d_in[1];
    const float* W_hh   = (const float*)d_in[2];
    const float* b_ih   = (const float*)d_in[3];
    const float* b_hh   = (const float*)d_in[4];
    const float* W_out  = (const float*)d_in[5];
    const float* b_out  = (const float*)d_in[6];
    float* out = (float*)d_out;

    static int attr_done = 0;
    if (!attr_done) {
        cudaFuncSetAttribute(lstm_recurrent,
                             cudaFuncAttributeMaxDynamicSharedMemorySize, RSMEM_BYTES);
        attr_done = 1;
    }

    reset_kernel<<<16, 256>>>(b_ih, b_hh);

    gemm_xgate<<<dim3(G4 / 128, T_STEPS), 256>>>(inputs, W_ih);

    lstm_recurrent<<<NCTA, 512, RSMEM_BYTES>>>(W_hh, out);

    gemm_out<<<dim3(OUT_DIM / 128, T_STEPS), 256>>>(W_out, b_out, out);
}

// round 12
// speedup vs baseline: 1.1829x; 1.1724x over previous
#include <cuda_runtime.h>
#include <cstdint>

#define T_STEPS 512
#define BATCH   64
#define IN_DIM  256
#define HID     512
#define OUT_DIM 256
#define G4      2048
#define NCTA    128

#define SW2_STRIDE  1032
#define SW2_FLOATS  (16 * SW2_STRIDE)      // 16512
#define SRED_STRIDE 36
#define SRED_FLOATS (256 * SRED_STRIDE)    // 9216
#define RSMEM_BYTES ((SW2_FLOATS + SRED_FLOATS) * 4)   // 102912

#define OFF_H ((size_t)T_STEPS * BATCH * OUT_DIM)
#define OFF_C (OFF_H + (size_t)BATCH * HID)

typedef unsigned long long ull;

__device__ float    g_xg[(size_t)T_STEPS * G4 * BATCH];   // [t][g][b]
__device__ float    g_hs[(size_t)T_STEPS * HID * BATCH];  // [t][k][b]
__device__ float    g_bsum[G4];
__device__ unsigned g_bar;
__device__ unsigned g_flag;

__device__ __forceinline__ void ffma2(ull& d, ull a, ull b) {
    asm("fma.rn.f32x2 %0, %1, %2, %0;" : "+l"(d) : "l"(a), "l"(b));
}
__device__ __forceinline__ float2 unpack2(ull v) {
    float2 r; asm("mov.b64 {%0, %1}, %2;" : "=f"(r.x), "=f"(r.y) : "l"(v)); return r;
}
__device__ __forceinline__ float sigf(float x) {
    return __fdividef(1.f, 1.f + __expf(-x));
}
__device__ __forceinline__ float tanhfast(float x) {
    float e = __expf(-2.f * fabsf(x));
    float r = __fdividef(1.f - e, 1.f + e);
    return copysignf(r, x);
}

__global__ void reset_kernel(const float* __restrict__ b_ih,
                             const float* __restrict__ b_hh) {
    int idx = blockIdx.x * blockDim.x + threadIdx.x;
    if (idx == 0) { g_bar = 0u; g_flag = 0u; }
    if (idx < G4) g_bsum[idx] = b_ih[idx] + b_hh[idx];
}

// ================= gemm1 (R5-proven): g_xg[t][g][b] = W_ih·x + bsum =========
__global__ __launch_bounds__(256) void gemm_xgate(
    const float* __restrict__ inp, const float* __restrict__ W)
{
    __shared__ float As[16][132];
    __shared__ float Bsw[16 * 196];
    const int t  = blockIdx.y;
    const int m0 = blockIdx.x * 128;
    const int tid = threadIdx.x;
    const int tx = tid & 15, ty = tid >> 4;
    const float* B = inp + (size_t)t * BATCH * IN_DIM;

    ull acc[4][4];
    #pragma unroll
    for (int i = 0; i < 4; i++)
        #pragma unroll
        for (int n = 0; n < 4; n++) acc[i][n] = 0ull;

    const int rr = tid >> 2;
    const int kq = (tid & 3) << 2;
    const int bbase = (rr >> 2) * 12 + (rr & 3) * 2;

    for (int k0 = 0; k0 < IN_DIM; k0 += 16) {
        #pragma unroll
        for (int u = 0; u < 2; u++) {
            int f4 = u * 256 + tid;
            int r2 = f4 >> 2, k2 = (f4 & 3) << 2;
            float4 v = *(const float4*)(W + (size_t)(m0 + r2) * IN_DIM + k0 + k2);
            As[k2 + 0][r2] = v.x; As[k2 + 1][r2] = v.y;
            As[k2 + 2][r2] = v.z; As[k2 + 3][r2] = v.w;
        }
        {
            float4 v = *(const float4*)(B + (size_t)rr * IN_DIM + k0 + kq);
            *(float2*)&Bsw[(kq + 0) * 196 + bbase] = make_float2(v.x, v.x);
            *(float2*)&Bsw[(kq + 1) * 196 + bbase] = make_float2(v.y, v.y);
            *(float2*)&Bsw[(kq + 2) * 196 + bbase] = make_float2(v.z, v.z);
            *(float2*)&Bsw[(kq + 3) * 196 + bbase] = make_float2(v.w, v.w);
        }
        __syncthreads();
        #pragma unroll
        for (int kk = 0; kk < 16; kk++) {
            ulonglong2 a01 = *(const ulonglong2*)&As[kk][ty * 8];
            ulonglong2 a23 = *(const ulonglong2*)&As[kk][ty * 8 + 4];
            const float* bp = Bsw + kk * 196 + tx * 12;
            ulonglong2 b01 = *(const ulonglong2*)bp;
            ulonglong2 b23 = *(const ulonglong2*)(bp + 4);
            ffma2(acc[0][0], a01.x, b01.x); ffma2(acc[1][0], a01.y, b01.x);
            ffma2(acc[2][0], a23.x, b01.x); ffma2(acc[3][0], a23.y, b01.x);
            ffma2(acc[0][1], a01.x, b01.y); ffma2(acc[1][1], a01.y, b01.y);
            ffma2(acc[2][1], a23.x, b01.y); ffma2(acc[3][1], a23.y, b01.y);
            ffma2(acc[0][2], a01.x, b23.x); ffma2(acc[1][2], a01.y, b23.x);
            ffma2(acc[2][2], a23.x, b23.x); ffma2(acc[3][2], a23.y, b23.x);
            ffma2(acc[0][3], a01.x, b23.y); ffma2(acc[1][3], a01.y, b23.y);
            ffma2(acc[2][3], a23.x, b23.y); ffma2(acc[3][3], a23.y, b23.y);
        }
        __syncthreads();
    }

    float* C = g_xg + ((size_t)t * G4 + m0) * BATCH;
    #pragma unroll
    for (int mp = 0; mp < 4; mp++) {
        float2 u0 = unpack2(acc[mp][0]);
        float2 u1 = unpack2(acc[mp][1]);
        float2 u2 = unpack2(acc[mp][2]);
        float2 u3 = unpack2(acc[mp][3]);
        int mA = ty * 8 + mp * 2, mB = mA + 1;
        float bA = g_bsum[m0 + mA], bB = g_bsum[m0 + mB];
        *(float4*)(C + (size_t)mA * BATCH + tx * 4) =
            make_float4(u0.x + bA, u1.x + bA, u2.x + bA, u3.x + bA);
        *(float4*)(C + (size_t)mB * BATCH + tx * 4) =
            make_float4(u0.y + bB, u1.y + bB, u2.y + bB, u3.y + bB);
    }
}

// ================= gemm2 (R5-proven): out[t][b][o] = h·W_out^T + b_out ======
__global__ __launch_bounds__(256) void gemm_out(
    const float* __restrict__ Wout, const float* __restrict__ bout,
    float* __restrict__ out)
{
    __shared__ float As2[16][68];
    __shared__ float Wsw[16 * 196];
    const int t  = blockIdx.y;
    const int n0 = blockIdx.x * 64;
    const int tid = threadIdx.x;
    const int tx = tid & 15, ty = tid >> 4;
    const float* A = g_hs + (size_t)t * HID * BATCH;

    ull acc[2][4];
    #pragma unroll
    for (int i = 0; i < 2; i++)
        #pragma unroll
        for (int n = 0; n < 4; n++) acc[i][n] = 0ull;

    const int rr = tid >> 2;
    const int kq = (tid & 3) << 2;
    const int obase = (rr >> 2) * 12 + (rr & 3) * 2;
    const int akk = tid >> 4, ac4 = (tid & 15) * 4;

    for (int k0 = 0; k0 < HID; k0 += 16) {
        *(float4*)&As2[akk][ac4] = *(const float4*)(A + (size_t)(k0 + akk) * BATCH + ac4);
        {
            float4 v = *(const float4*)(Wout + (size_t)(n0 + rr) * HID + k0 + kq);
            *(float2*)&Wsw[(kq + 0) * 196 + obase] = make_float2(v.x, v.x);
            *(float2*)&Wsw[(kq + 1) * 196 + obase] = make_float2(v.y, v.y);
            *(float2*)&Wsw[(kq + 2) * 196 + obase] = make_float2(v.z, v.z);
            *(float2*)&Wsw[(kq + 3) * 196 + obase] = make_float2(v.w, v.w);
        }
        __syncthreads();
        #pragma unroll
        for (int kk = 0; kk < 16; kk++) {
            ulonglong2 a = *(const ulonglong2*)&As2[kk][ty * 4];
            const float* wp = Wsw + kk * 196 + tx * 12;
            ulonglong2 w01 = *(const ulonglong2*)wp;
            ulonglong2 w23 = *(const ulonglong2*)(wp + 4);
            ffma2(acc[0][0], a.x, w01.x); ffma2(acc[1][0], a.y, w01.x);
            ffma2(acc[0][1], a.x, w01.y); ffma2(acc[1][1], a.y, w01.y);
            ffma2(acc[0][2], a.x, w23.x); ffma2(acc[1][2], a.y, w23.x);
            ffma2(acc[0][3], a.x, w23.y); ffma2(acc[1][3], a.y, w23.y);
        }
        __syncthreads();
    }

    float4 bb = *(const float4*)(bout + n0 + tx * 4);
    float2 u[2][4];
    #pragma unroll
    for (int p = 0; p < 2; p++)
        #pragma unroll
        for (int n = 0; n < 4; n++) u[p][n] = unpack2(acc[p][n]);
    #pragma unroll
    for (int bi = 0; bi < 4; bi++) {
        int p = bi >> 1;
        float4 r;
        if (bi & 1) r = make_float4(u[p][0].y + bb.x, u[p][1].y + bb.y,
                                    u[p][2].y + bb.z, u[p][3].y + bb.w);
        else        r = make_float4(u[p][0].x + bb.x, u[p][1].x + bb.y,
                                    u[p][2].x + bb.z, u[p][3].x + bb.w);
        *(float4*)(out + ((size_t)t * BATCH + ty * 4 + bi) * OUT_DIM + n0 + tx * 4) = r;
    }
}

// ================= persistent recurrent kernel =================
// 256 threads = 8 warps; warp hk owns k-slice [64*hk, 64*hk+64).
// Thread: 2 columns (iip*2, iip*2+1) x 4 batches x 4 gates.
// Only ONE warp touches each (slice, batch) h line -> L2 traffic halved vs R5.
__device__ __forceinline__ void loadh8(ulonglong2* hb, const float* p) {
    #pragma unroll
    for (int i = 0; i < 8; i++)
        hb[i] = __ldg((const ulonglong2*)(p + (size_t)i * BATCH));
}

// acc[q][c][pair]; 8 k-steps; w rows q*4 + iip*2 + c
__device__ __forceinline__ void comp8x2(ull acc[4][2][2], const ulonglong2* hb,
                                        const float* wslice, int iip2, int kl) {
    #pragma unroll
    for (int q = 0; q < 4; q++) {
        #pragma unroll
        for (int c = 0; c < 2; c++) {
            const float* wr = wslice + (q * 4 + iip2 + c) * SW2_STRIDE + 2 * kl;
            ulonglong2 w0 = *(const ulonglong2*)(wr);
            ulonglong2 w1 = *(const ulonglong2*)(wr + 4);
            ulonglong2 w2 = *(const ulonglong2*)(wr + 8);
            ulonglong2 w3 = *(const ulonglong2*)(wr + 12);
            ffma2(acc[q][c][0], hb[0].x, w0.x); ffma2(acc[q][c][1], hb[0].y, w0.x);
            ffma2(acc[q][c][0], hb[1].x, w0.y); ffma2(acc[q][c][1], hb[1].y, w0.y);
            ffma2(acc[q][c][0], hb[2].x, w1.x); ffma2(acc[q][c][1], hb[2].y, w1.x);
            ffma2(acc[q][c][0], hb[3].x, w1.y); ffma2(acc[q][c][1], hb[3].y, w1.y);
            ffma2(acc[q][c][0], hb[4].x, w2.x); ffma2(acc[q][c][1], hb[4].y, w2.x);
            ffma2(acc[q][c][0], hb[5].x, w2.y); ffma2(acc[q][c][1], hb[5].y, w2.y);
            ffma2(acc[q][c][0], hb[6].x, w3.x); ffma2(acc[q][c][1], hb[6].y, w3.x);
            ffma2(acc[q][c][0], hb[7].x, w3.y); ffma2(acc[q][c][1], hb[7].y, w3.y);
        }
    }
}

__global__ void __launch_bounds__(256, 1)
lstm_recurrent(const float* __restrict__ W_hh, float* __restrict__ out)
{
    extern __shared__ float smem[];
    float* sW2  = smem;                 // 16 x 1032 (splatted W_hh rows)
    float* sRed = smem + SW2_FLOATS;    // 256 x 36

    const int tid = threadIdx.x;
    const int j0  = blockIdx.x << 2;
    // FMA role
    const int hk   = tid >> 5;          // warp = slice 0..7
    const int lane = tid & 31;
    const int iip  = lane >> 4;         // column pair: 0 -> cols {0,1}, 1 -> {2,3}
    const int bg   = (lane & 15) << 2;  // batches bg..bg+3
    // epilogue role: one (column, batch) output per thread
    const int jj  = tid >> 6;           // 0..3
    const int bo  = tid & 63;
    const int j_out = j0 + jj;
    const int erow = (jj >> 1) * 16 + (bo >> 2);   // lane that produced it
    const int eoff = (jj & 1) * 16 + (bo & 3) * 4;

    // stage W_hh pre-splatted: row r = q*4+iw  <- W_hh[q*512 + j0+iw][:]
    #pragma unroll
    for (int u = 0; u < 8; u++) {
        int f4 = u * 256 + tid;
        int rr = f4 >> 7;
        int kk = (f4 & 127) << 2;
        int q = rr >> 2, iw = rr & 3;
        float4 v = *(const float4*)(W_hh + (size_t)(q * HID + j0 + iw) * HID + kk);
        float* d = sW2 + rr * SW2_STRIDE + 2 * kk;
        *(float4*)(d    ) = make_float4(v.x, v.x, v.y, v.y);
        *(float4*)(d + 4) = make_float4(v.z, v.z, v.w, v.w);
    }
    __syncthreads();

    float creg = 0.f;
    const float* wslice = sW2 + hk * 128;   // slice k-offset within splatted rows
    const int iip2 = iip * 2;

    for (int t = 0; t < T_STEPS; t++) {
        // xg for this thread's output (load early; hidden under FMA loop)
        float xg[4];
        #pragma unroll
        for (int q = 0; q < 4; q++)
            xg[q] = __ldg(g_xg + ((size_t)t * G4 + q * HID + j_out) * BATCH + bo);

        ull acc[4][2][2];
        #pragma unroll
        for (int q = 0; q < 4; q++)
            #pragma unroll
            for (int c = 0; c < 2; c++) { acc[q][c][0] = 0ull; acc[q][c][1] = 0ull; }

        if (t > 0) {
            const float* hsrc = g_hs + ((size_t)(t - 1) * HID + hk * 64) * BATCH + bg;
            ulonglong2 hb0[8], hb1[8];
            loadh8(hb0, hsrc);
            #pragma unroll
            for (int g2 = 0; g2 < 4; g2++) {
                loadh8(hb1, hsrc + (size_t)(2 * g2 + 1) * 8 * BATCH);
                comp8x2(acc, hb0, wslice, iip2, 2 * g2 * 8);
                loadh8(hb0, hsrc + (size_t)(2 * g2 + 2) * 8 * BATCH);  // overread stays in-array
                comp8x2(acc, hb1, wslice, iip2, (2 * g2 + 1) * 8);
            }
        }

        // publish partials: sRed[tid][c*16 + bb*4 + q]
        {
            float* p = sRed + tid * SRED_STRIDE;
            #pragma unroll
            for (int c = 0; c < 2; c++) {
                float2 q0l = unpack2(acc[0][c][0]), q0h = unpack2(acc[0][c][1]);
                float2 q1l = unpack2(acc[1][c][0]), q1h = unpack2(acc[1][c][1]);
                float2 q2l = unpack2(acc[2][c][0]), q2h = unpack2(acc[2][c][1]);
                float2 q3l = unpack2(acc[3][c][0]), q3h = unpack2(acc[3][c][1]);
                *(float4*)(p + c * 16 + 0)  = make_float4(q0l.x, q1l.x, q2l.x, q3l.x);
                *(float4*)(p + c * 16 + 4)  = make_float4(q0l.y, q1l.y, q2l.y, q3l.y);
                *(float4*)(p + c * 16 + 8)  = make_float4(q0h.x, q1h.x, q2h.x, q3h.x);
                *(float4*)(p + c * 16 + 12) = make_float4(q0h.y, q1h.y, q2h.y, q3h.y);
            }
        }
        __syncthreads();

        // epilogue: one output per thread, reduce over 8 slices
        {
            const float* rp = sRed + erow * SRED_STRIDE + eoff;
            float4 v0 = *(const float4*)(rp);
            float4 v1 = *(const float4*)(rp + 32 * SRED_STRIDE);
            float4 v2 = *(const float4*)(rp + 64 * SRED_STRIDE);
            float4 v3 = *(const float4*)(rp + 96 * SRED_STRIDE);
            float4 v4 = *(const float4*)(rp + 128 * SRED_STRIDE);
            float4 v5 = *(const float4*)(rp + 160 * SRED_STRIDE);
            float4 v6 = *(const float4*)(rp + 192 * SRED_STRIDE);
            float4 v7 = *(const float4*)(rp + 224 * SRED_STRIDE);
            float a0 = ((v0.x + v1.x) + (v2.x + v3.x)) + ((v4.x + v5.x) + (v6.x + v7.x)) + xg[0];
            float a1 = ((v0.y + v1.y) + (v2.y + v3.y)) + ((v4.y + v5.y) + (v6.y + v7.y)) + xg[1];
            float a2 = ((v0.z + v1.z) + (v2.z + v3.z)) + ((v4.z + v5.z) + (v6.z + v7.z)) + xg[2];
            float a3 = ((v0.w + v1.w) + (v2.w + v3.w)) + ((v4.w + v5.w) + (v6.w + v7.w)) + xg[3];
            float iv = sigf(a0);
            float fv = sigf(a1);
            float gv = tanhfast(a2);
            float ov = sigf(a3);
            creg = fv * creg + iv * gv;
            float hn = ov * tanhfast(creg);
            g_hs[((size_t)t * HID + j_out) * BATCH + bo] = hn;
            if (t == T_STEPS - 1) {
                out[OFF_H + (size_t)bo * HID + j_out] = hn;
                out[OFF_C + (size_t)bo * HID + j_out] = creg;
            }
        }
        __syncthreads();

        // grid barrier: single release-atomic + flag (R5-proven)
        if (tid == 0) {
            unsigned target = (unsigned)(t + 1) * NCTA;
            unsigned ret;
            asm volatile("atom.release.gpu.global.add.u32 %0, [%1], %2;"
                         : "=r"(ret) : "l"(&g_bar), "r"(1u) : "memory");
            if (ret == target - 1) {
                asm volatile("st.release.gpu.global.u32 [%0], %1;"
                             :: "l"(&g_flag), "r"((unsigned)(t + 1)) : "memory");
            } else {
                unsigned v;
                do {
                    asm volatile("ld.acquire.gpu.global.u32 %0, [%1];"
                                 : "=r"(v) : "l"(&g_flag) : "memory");
                } while (v < (unsigned)(t + 1));
            }
        }
        __syncthreads();
    }
}

// ---------------- launch ----------------
extern "C" void kernel_launch(void* const* d_in, const int* in_sizes, int n_in,
                              void* d_out, int out_size) {
    const float* inputs = (const float*)d_in[0];
    const float* W_ih   = (const float*)d_in[1];
    const float* W_hh   = (const float*)d_in[2];
    const float* b_ih   = (const float*)d_in[3];
    const float* b_hh   = (const float*)d_in[4];
    const float* W_out  = (const float*)d_in[5];
    const float* b_out  = (const float*)d_in[6];
    float* out = (float*)d_out;

    static int attr_done = 0;
    if (!attr_done) {
        cudaFuncSetAttribute(lstm_recurrent,
                             cudaFuncAttributeMaxDynamicSharedMemorySize, RSMEM_BYTES);
        attr_done = 1;
    }

    reset_kernel<<<16, 256>>>(b_ih, b_hh);

    gemm_xgate<<<dim3(G4 / 128, T_STEPS), 256>>>(inputs, W_ih);

    lstm_recurrent<<<NCTA, 256, RSMEM_BYTES>>>(W_hh, out);

    gemm_out<<<dim3(OUT_DIM / 64, T_STEPS), 256>>>(W_out, b_out, out);
}